// round 4
// baseline (speedup 1.0000x reference)
#include <cuda_runtime.h>
#include <math.h>

#define NB    32
#define SL    20
#define DIM   256
#define BEAMW 4
#define G     128          // persistent grid (1 block/SM)
#define NT    512          // 4 teams x 128 threads
#define EPSC  1e-8f
#define LNEPS 1e-5f

// per-team smem: sA2 dup (64kk x 32rows x float2 = 16KB) + sB (64kk x 64cols = 16KB)
#define TEAM_BYTES 32768
#define SMEM_DYN   (4 * TEAM_BYTES)

// ---------------- static device scratch ----------------
__device__ float d_seq[NB * SL * DIM];
__device__ float d_stk[2][NB * BEAMW * SL * DIM];
__device__ int   d_p[2][NB * BEAMW];
__device__ int   d_q[2][NB * BEAMW];
__device__ float d_win[128 * 768];
__device__ float d_cc[128 * 512];
__device__ float d_cpart[3 * 128 * 256];     // conv partials (ks3)
__device__ float d_inter[128 * 1024];        // gelu(cc @ wcell1 + b)
__device__ float d_c2[2 * 128 * 1024];       // cell2 partials (ks2)
__device__ float d_bscore[NB * BEAMW];
__device__ unsigned g_cnt = 0;
__device__ unsigned g_gen = 0;

// ---------------- grid barrier ----------------
__device__ __forceinline__ void gbar() {
    __syncthreads();
    if (threadIdx.x == 0) {
        volatile unsigned* gen = &g_gen;
        unsigned my = *gen;
        __threadfence();
        if (atomicAdd(&g_cnt, 1u) == (unsigned)(G - 1)) {
            g_cnt = 0;
            __threadfence();
            *gen = my + 1u;
        } else {
            while (*gen == my) { __nanosleep(32); }
        }
        __threadfence();
    }
    __syncthreads();
}

// ---------------- helpers ----------------
__device__ __forceinline__ float geluf(float x) {
    return 0.5f * x * (1.0f + erff(x * 0.7071067811865476f));
}
__device__ __forceinline__ float sigmoidf_(float x) {
    return 1.0f / (1.0f + expf(-x));
}

// two independent 256-thread halves; returns the half-sum
__device__ __forceinline__ float halfReduceSum(float v, float* sbuf) {
    int tid = threadIdx.x;
    #pragma unroll
    for (int o = 16; o > 0; o >>= 1) v += __shfl_down_sync(0xffffffffu, v, o);
    if ((tid & 31) == 0) sbuf[tid >> 5] = v;
    __syncthreads();
    int h = tid >> 8;
    float r = 0.f;
    #pragma unroll
    for (int w = 0; w < 8; w++) r += sbuf[h * 8 + w];
    __syncthreads();
    return r;
}

// ---------------- packed f32x2 FFMA ----------------
__device__ __forceinline__ void fma2(unsigned long long& d, unsigned long long a,
                                     unsigned long long b) {
    asm("fma.rn.f32x2 %0, %1, %2, %0;" : "+l"(d) : "l"(a), "l"(b));
}
__device__ __forceinline__ void unpack2(unsigned long long v, float& lo, float& hi) {
    asm("mov.b64 {%0, %1}, %2;" : "=f"(lo), "=f"(hi) : "l"(v));
}

// ---------------- 32x64 tile GEMM, K split over 4 teams of 128 threads ----------------
// thread (ttid = rp*8+cg): rows {2rp, 2rp+1} x cols {cg*8..cg*8+7}
// nch = chunks of 64 K per team; team t covers k0 + t*nch*64 ...
__device__ void gemm_tile(const float* __restrict__ A, int lda,
                          const float* __restrict__ Bw, int ldb,
                          int k0, int nch,
                          float* __restrict__ C, int ldc,
                          const float* __restrict__ bias, int act,
                          char* dsm) {
    int tid  = threadIdx.x;
    int team = tid >> 7;
    int ttid = tid & 127;
    int rp = ttid >> 3;          // 0..15
    int cg = ttid & 7;           // 0..7
    float* sA2 = (float*)(dsm + team * TEAM_BYTES);           // dup pairs [64][32] f32x2
    float* sB  = (float*)(dsm + team * TEAM_BYTES + 16384);   // [64][64] f32

    int kbase = k0 + team * nch * 64;
    unsigned long long acc[8];
    #pragma unroll
    for (int i = 0; i < 8; i++) acc[i] = 0ull;

    // staging indices
    int ar = ttid & 31, ak4 = ttid >> 5;     // + e*4 for e in 0..3 -> k4 0..15
    int bc4 = ttid & 15, bk = ttid >> 4;     // + e*8 for e in 0..7 -> bk 0..63
    float4 ra[4], rb[8];
    #pragma unroll
    for (int e = 0; e < 4; e++)
        ra[e] = *(const float4*)(A + (size_t)ar * lda + kbase + (ak4 + e * 4) * 4);
    #pragma unroll
    for (int e = 0; e < 8; e++)
        rb[e] = *(const float4*)(Bw + (size_t)(kbase + bk + e * 8) * ldb + bc4 * 4);

    for (int ch = 0; ch < nch; ch++) {
        // stage A (duplicated f32x2) and B
        {
            float2* pa = (float2*)sA2;
            #pragma unroll
            for (int e = 0; e < 4; e++) {
                int k4 = (ak4 + e * 4) * 4;
                pa[(k4 + 0) * 32 + ar] = make_float2(ra[e].x, ra[e].x);
                pa[(k4 + 1) * 32 + ar] = make_float2(ra[e].y, ra[e].y);
                pa[(k4 + 2) * 32 + ar] = make_float2(ra[e].z, ra[e].z);
                pa[(k4 + 3) * 32 + ar] = make_float2(ra[e].w, ra[e].w);
            }
            #pragma unroll
            for (int e = 0; e < 8; e++)
                *(float4*)(sB + (bk + e * 8) * 64 + bc4 * 4) = rb[e];
        }
        __syncthreads();
        if (ch + 1 < nch) {
            int kn = kbase + (ch + 1) * 64;
            #pragma unroll
            for (int e = 0; e < 4; e++)
                ra[e] = *(const float4*)(A + (size_t)ar * lda + kn + (ak4 + e * 4) * 4);
            #pragma unroll
            for (int e = 0; e < 8; e++)
                rb[e] = *(const float4*)(Bw + (size_t)(kn + bk + e * 8) * ldb + bc4 * 4);
        }
        #pragma unroll
        for (int kk = 0; kk < 64; kk++) {
            ulonglong2 arow = *(const ulonglong2*)(sA2 + kk * 64 + rp * 4);
            ulonglong2 b01  = *(const ulonglong2*)(sB + kk * 64 + cg * 8);
            ulonglong2 b23  = *(const ulonglong2*)(sB + kk * 64 + cg * 8 + 4);
            fma2(acc[0], arow.x, b01.x);
            fma2(acc[1], arow.x, b01.y);
            fma2(acc[2], arow.x, b23.x);
            fma2(acc[3], arow.x, b23.y);
            fma2(acc[4], arow.y, b01.x);
            fma2(acc[5], arow.y, b01.y);
            fma2(acc[6], arow.y, b23.x);
            fma2(acc[7], arow.y, b23.y);
        }
        __syncthreads();
    }

    // cross-team combine: teams 1-3 write outputs to their own sB region; team0 sums
    float o[16];
    #pragma unroll
    for (int i = 0; i < 8; i++) unpack2(acc[i], o[2 * i], o[2 * i + 1]);
    if (team != 0) {
        float* cb = sB;   // this team's region, layout [j][ttid]
        #pragma unroll
        for (int j = 0; j < 16; j++) cb[j * 128 + ttid] = o[j];
    }
    __syncthreads();
    if (team == 0) {
        #pragma unroll
        for (int tt = 1; tt < 4; tt++) {
            const float* cb = (const float*)(dsm + tt * TEAM_BYTES + 16384);
            #pragma unroll
            for (int j = 0; j < 16; j++) o[j] += cb[j * 128 + ttid];
        }
        // o[0..3]=row 2rp cols cg*8+0..3 (acc0,1); o[4..7]=+4..7; o[8..15]=row 2rp+1
        float bb[8];
        if (bias) {
            #pragma unroll
            for (int j = 0; j < 8; j++) bb[j] = bias[cg * 8 + j];
        } else {
            #pragma unroll
            for (int j = 0; j < 8; j++) bb[j] = 0.f;
        }
        float r0[8], r1[8];
        #pragma unroll
        for (int j = 0; j < 8; j++) { r0[j] = o[j] + bb[j]; r1[j] = o[8 + j] + bb[j]; }
        if (act) {
            #pragma unroll
            for (int j = 0; j < 8; j++) { r0[j] = geluf(r0[j]); r1[j] = geluf(r1[j]); }
        }
        *(float4*)(C + (size_t)(2 * rp) * ldc + cg * 8)         = make_float4(r0[0], r0[1], r0[2], r0[3]);
        *(float4*)(C + (size_t)(2 * rp) * ldc + cg * 8 + 4)     = make_float4(r0[4], r0[5], r0[6], r0[7]);
        *(float4*)(C + (size_t)(2 * rp + 1) * ldc + cg * 8)     = make_float4(r1[0], r1[1], r1[2], r1[3]);
        *(float4*)(C + (size_t)(2 * rp + 1) * ldc + cg * 8 + 4) = make_float4(r1[4], r1[5], r1[6], r1[7]);
    }
    __syncthreads();
}

// ---------------- the persistent mega kernel ----------------
__global__ void __launch_bounds__(NT, 1)
mega(const float* __restrict__ sequence, const float* __restrict__ input_mask,
     const float* __restrict__ w_init, const float* __restrict__ b_init,
     const float* __restrict__ ln1_g, const float* __restrict__ ln1_b,
     const float* __restrict__ scorer_w, const float* __restrict__ scorer_b,
     const float* __restrict__ conv_w, const float* __restrict__ conv_b,
     const float* __restrict__ start,
     const float* __restrict__ wcell1_w, const float* __restrict__ wcell1_b,
     const float* __restrict__ wcell2_w, const float* __restrict__ wcell2_b,
     const float* __restrict__ ln2_g, const float* __restrict__ ln2_b,
     float* __restrict__ out) {
    extern __shared__ char dsm[];
    __shared__ float sred[16];
    __shared__ float sscore[8];
    __shared__ int   ssel[BEAMW];

    int tid = threadIdx.x;
    int bid = blockIdx.x;
    int h   = tid >> 8;        // half id (for EF / LN1)
    int col = tid & 255;

    // ---- init 1: seq = LN1(sequence @ w_init + b_init); one row per half ----
    {
        float* sX = (float*)dsm;
        for (int job = bid; job < (NB * SL) / 2; job += G) {
            int row = job * 2 + h;
            sX[h * 256 + col] = sequence[(size_t)row * DIM + col];
            __syncthreads();
            float acc = 0.f;
            for (int i = 0; i < DIM; i++)
                acc += sX[h * 256 + i] * w_init[i * DIM + col];
            float y = acc + b_init[col];
            float s1 = halfReduceSum(y, sred);
            float s2 = halfReduceSum(y * y, sred);
            float m = s1 * (1.0f / DIM);
            float var = s2 * (1.0f / DIM) - m * m;
            d_seq[(size_t)row * DIM + col] = (y - m) * rsqrtf(var + LNEPS) * ln1_g[col] + ln1_b[col];
            __syncthreads();
        }
    }
    gbar();

    // ---- init 2: stack init + first gather (K=1) ----
    if (bid < NB) {
        int n = bid;
        float* stk0 = d_stk[0] + (size_t)(n * BEAMW) * SL * DIM;
        if (h == 0) {
            stk0[col]       = d_seq[(size_t)(n * SL + 0) * DIM + col];
            stk0[DIM + col] = d_seq[(size_t)(n * SL + 1) * DIM + col];
            if (col == 0) {
                d_p[0][n * BEAMW] = (input_mask[n * SL + 1] > 0.5f) ? 1 : 0;
                d_q[0][n * BEAMW] = 0;
            }
        }
        __syncthreads();
        if (h == 0) {
            int p = d_p[0][n * BEAMW];
            float c1 = (p >= 1) ? stk0[(p - 1) * DIM + col] : start[col];
            float c2 = stk0[p * DIM + col];
            float cu = d_seq[(size_t)(n * SL + 2) * DIM + col];
            d_win[n * 768 + col]       = c1;
            d_win[n * 768 + 256 + col] = c2;
            d_win[n * 768 + 512 + col] = cu;
            d_cc[n * 512 + col]        = c1;
            d_cc[n * 512 + 256 + col]  = c2;
        }
    }
    gbar();

    int K = 1, buf = 0;
    for (int t = 2; t <= 2 * SL - 2; t++) {
        int M  = NB * K;
        int rt = M / 32;
        int newK = (2 * K < BEAMW) ? 2 * K : BEAMW;

        // ---- phase B: cell1 (full K, fused gelu) + conv partials (ks3) ----
        int c1Jobs = rt * 16;            // 32x64 tiles over N=1024
        int cvJobs = rt * 4 * 3;         // 32x64 tiles over N=256, K split x3
        for (int job = bid; job < c1Jobs + cvJobs; job += G) {
            if (job < c1Jobs) {
                int ri = job >> 4, ct = job & 15;
                gemm_tile(d_cc + (size_t)ri * 32 * 512, 512,
                          wcell1_w + ct * 64, 1024,
                          0, 2,
                          d_inter + (size_t)ri * 32 * 1024 + ct * 64, 1024,
                          wcell1_b + ct * 64, 1, dsm);
            } else {
                int j = job - c1Jobs;
                int ks = j % 3, r2 = j / 3;
                int ct = r2 & 3, ri = r2 >> 2;
                gemm_tile(d_win + (size_t)ri * 32 * 768, 768,
                          conv_w + ct * 64, 256,
                          ks * 256, 1,
                          d_cpart + (size_t)ks * 32768 + (size_t)ri * 32 * 256 + ct * 64, 256,
                          nullptr, 0, dsm);
            }
        }
        gbar();

        // ---- phase C: cell2 partials (ks2) ----
        for (int job = bid; job < rt * 32; job += G) {
            int ks = job & 1, ct = (job >> 1) & 15, ri = job >> 5;
            gemm_tile(d_inter + (size_t)ri * 32 * 1024 + ks * 512, 1024,
                      wcell2_w + (size_t)ks * 512 * 1024 + ct * 64, 1024,
                      0, 2,
                      d_c2 + (size_t)ks * 131072 + (size_t)ri * 32 * 1024 + ct * 64, 1024,
                      nullptr, 0, dsm);
        }
        gbar();

        // ---- phase EF: score finalize + compose + top-k + beam copy + next gather ----
        if (bid < NB) {
            int n = bid;
            float* red = (float*)dsm;    // [BEAMW][256]

            // 1. scores (two beams at a time, one per half)
            for (int k0 = 0; k0 < K; k0 += 2) {
                int k = k0 + h;
                int valid = (k < K);
                int kk2 = valid ? k : 0;
                int m = n * K + kk2;
                float s = d_cpart[m * 256 + col]
                        + d_cpart[32768 + m * 256 + col]
                        + d_cpart[65536 + m * 256 + col];
                float y = valid ? geluf(s + conv_b[col]) * scorer_w[col] : 0.f;
                float dot = halfReduceSum(y, sred);
                if (col == 0 && valid) {
                    float dec = sigmoidf_(dot + scorer_b[0]);
                    int p = d_p[buf][n * BEAMW + k];
                    int q = d_q[buf][n * BEAMW + k];
                    float lp  = (p >= 1) ? 1.0f : 0.0f;
                    float cmf = (q < SL - 2) ? input_mask[n * SL + 2 + q] : 0.0f;
                    float bz  = ((lp == 0.0f) && (cmf == 0.0f)) ? 1.0f : 0.0f;
                    float rs = cmf * dec + (1.0f - cmf);
                    rs = lp * rs;
                    rs = bz + (1.0f - bz) * rs;
                    rs = logf(rs + EPSC);
                    float ss = lp * (1.0f - dec) + (1.0f - lp);
                    ss = cmf * ss;
                    ss = (1.0f - bz) * ss;
                    ss = logf(ss + EPSC);
                    sscore[k] = rs;
                    sscore[4 + k] = ss;
                }
            }
            // 2. compose (sum cell2 partials + bias -> gates + LN2)
            for (int k0 = 0; k0 < K; k0 += 2) {
                int k = k0 + h;
                int valid = (k < K);
                int kk2 = valid ? k : 0;
                int m = n * K + kk2;
                const float* c20 = d_c2 + (size_t)m * 1024;
                const float* c21 = d_c2 + 131072 + (size_t)m * 1024;
                float v0 = c20[col]       + c21[col]       + wcell2_b[col];
                float v1 = c20[256 + col] + c21[256 + col] + wcell2_b[256 + col];
                float v2 = c20[512 + col] + c21[512 + col] + wcell2_b[512 + col];
                float v3 = c20[768 + col] + c21[768 + col] + wcell2_b[768 + col];
                float x = sigmoidf_(v0) * d_cc[m * 512 + col]
                        + sigmoidf_(v1) * d_cc[m * 512 + 256 + col]
                        + sigmoidf_(v2) * v3;
                float xm = valid ? x : 0.f;
                float s1 = halfReduceSum(xm, sred);
                float s2 = halfReduceSum(xm * xm, sred);
                if (valid) {
                    float mn = s1 * (1.0f / DIM);
                    float var = s2 * (1.0f / DIM) - mn * mn;
                    red[k * 256 + col] = (x - mn) * rsqrtf(var + LNEPS) * ln2_g[col] + ln2_b[col];
                }
            }
            __syncthreads();
            // 3. stable top-k
            if (tid == 0) {
                int C = 2 * K;
                float sc[8];
                for (int c = 0; c < C; c++)
                    sc[c] = (c < K) ? sscore[c] : sscore[4 + (c - K)];
                if (C <= BEAMW) {
                    for (int s = 0; s < C; s++) { ssel[s] = s; d_bscore[n * BEAMW + s] = sc[s]; }
                } else {
                    bool used[8];
                    for (int c = 0; c < C; c++) used[c] = false;
                    for (int s = 0; s < BEAMW; s++) {
                        int best = -1; float bv = 0.f;
                        for (int c = 0; c < C; c++) {
                            if (used[c]) continue;
                            if (best < 0 || sc[c] > bv) { best = c; bv = sc[c]; }
                        }
                        used[best] = true;
                        ssel[s] = best;
                        d_bscore[n * BEAMW + s] = bv;
                    }
                }
            }
            __syncthreads();
            // 4. beam copy (one beam per half)
            int nb2 = buf ^ 1;
            for (int s = h; s < newK; s += 2) {
                int c = ssel[s];
                int isred = (c < K);
                int k = isred ? c : (c - K);
                int p = d_p[buf][n * BEAMW + k];
                int q = d_q[buf][n * BEAMW + k];
                int lp = (p >= 1);
                float cmf = (q < SL - 2) ? input_mask[n * SL + 2 + q] : 0.0f;
                int cm = (cmf > 0.5f);
                int wr_pos = -1, newp = p, newq = q;
                const float* wr_g = nullptr;
                int wr_sm = 0;
                if (isred) {
                    if (lp) { wr_pos = p - 1; newp = p - 1; wr_sm = 1; }
                } else {
                    newq = q + 1;
                    if (cm) { wr_pos = p + 1; newp = p + 1; wr_g = &d_seq[(size_t)(n * SL + 2 + q) * DIM]; }
                }
                const float* src = d_stk[buf] + (size_t)(n * BEAMW + k) * SL * DIM;
                float* dst       = d_stk[nb2] + (size_t)(n * BEAMW + s) * SL * DIM;
                int len = (newp + 1) * DIM;
                for (int idx = col; idx < len; idx += 256) {
                    int pos = idx >> 8;
                    float v = (pos == wr_pos) ? (wr_sm ? red[k * 256 + (idx & 255)]
                                                       : wr_g[idx & 255])
                                              : src[idx];
                    dst[idx] = v;
                }
                if (col == 0) {
                    d_p[nb2][n * BEAMW + s] = newp;
                    d_q[nb2][n * BEAMW + s] = newq;
                }
            }
            __syncthreads();
            // 5. gather for next iteration
            for (int s = h; s < newK; s += 2) {
                int m2 = n * newK + s;
                int p = d_p[nb2][n * BEAMW + s];
                int q = d_q[nb2][n * BEAMW + s];
                const float* stk = d_stk[nb2] + (size_t)(n * BEAMW + s) * SL * DIM;
                float c1 = (p >= 1) ? stk[(p - 1) * DIM + col] : start[col];
                float c2 = stk[p * DIM + col];
                float cu = (q < SL - 2) ? d_seq[(size_t)(n * SL + 2 + q) * DIM + col] : 0.f;
                d_win[m2 * 768 + col]       = c1;
                d_win[m2 * 768 + 256 + col] = c2;
                d_win[m2 * 768 + 512 + col] = cu;
                d_cc[m2 * 512 + col]        = c1;
                d_cc[m2 * 512 + 256 + col]  = c2;
            }
        }
        gbar();
        buf ^= 1;
        K = newK;
    }

    // ---- final: softmax over beam scores, weighted top-of-stack sum ----
    if (bid < NB && h == 0) {
        int n = bid;
        float sc[BEAMW];
        float mx = -1e30f;
        #pragma unroll
        for (int k = 0; k < BEAMW; k++) {
            sc[k] = d_bscore[n * BEAMW + k];
            mx = fmaxf(mx, sc[k]);
        }
        float e[BEAMW], sum = 0.f;
        #pragma unroll
        for (int k = 0; k < BEAMW; k++) { e[k] = expf(sc[k] - mx); sum += e[k]; }
        float o = 0.f;
        #pragma unroll
        for (int k = 0; k < BEAMW; k++) {
            int p = d_p[buf][n * BEAMW + k];
            o += (e[k] / sum) * d_stk[buf][((size_t)(n * BEAMW + k) * SL + p) * DIM + col];
        }
        out[(size_t)n * DIM + col] = o;
    }
}

// ---------------- host launcher ----------------
extern "C" void kernel_launch(void* const* d_in, const int* in_sizes, int n_in,
                              void* d_out, int out_size) {
    const float* sequence   = (const float*)d_in[0];
    const float* input_mask = (const float*)d_in[1];
    const float* w_init     = (const float*)d_in[2];
    const float* b_init     = (const float*)d_in[3];
    const float* ln1_g      = (const float*)d_in[4];
    const float* ln1_b      = (const float*)d_in[5];
    const float* scorer_w   = (const float*)d_in[6];
    const float* scorer_b   = (const float*)d_in[7];
    const float* conv_w     = (const float*)d_in[8];
    const float* conv_b     = (const float*)d_in[9];
    const float* start      = (const float*)d_in[10];
    const float* wcell1_w   = (const float*)d_in[11];
    const float* wcell1_b   = (const float*)d_in[12];
    const float* wcell2_w   = (const float*)d_in[13];
    const float* wcell2_b   = (const float*)d_in[14];
    const float* ln2_g      = (const float*)d_in[15];
    const float* ln2_b      = (const float*)d_in[16];
    float* out = (float*)d_out;

    cudaFuncSetAttribute(mega, cudaFuncAttributeMaxDynamicSharedMemorySize, SMEM_DYN);
    mega<<<G, NT, SMEM_DYN>>>(sequence, input_mask, w_init, b_init, ln1_g, ln1_b,
                              scorer_w, scorer_b, conv_w, conv_b, start,
                              wcell1_w, wcell1_b, wcell2_w, wcell2_b, ln2_g, ln2_b, out);
}

// round 5
// speedup vs baseline: 1.3653x; 1.3653x over previous
#include <cuda_runtime.h>
#include <math.h>

#define NB    32
#define SL    20
#define DIM   256
#define BEAMW 4
#define G     128          // persistent grid (1 block/SM)
#define NT    512          // 4 teams x 128 threads
#define EPSC  1e-8f
#define LNEPS 1e-5f

// per-team smem: sA transposed [64 kk][68 pad] = 17408B + sB [64 kk][64] = 16384B
#define TEAM_BYTES 33792
#define SMEM_DYN   (4 * TEAM_BYTES)

// ---------------- static device scratch ----------------
__device__ float d_seq[NB * SL * DIM];
__device__ float d_stk[2][NB * BEAMW * SL * DIM];
__device__ int   d_p[2][NB * BEAMW];
__device__ int   d_q[2][NB * BEAMW];
__device__ float d_win[128 * 768];
__device__ float d_cc[128 * 512];
__device__ float d_cpart[3 * 128 * 256];     // conv raw partials (ks3)
__device__ float d_i1[2 * 128 * 1024];       // cell1 raw partials (ks2)
__device__ float d_c2[4 * 128 * 1024];       // cell2 raw partials (ks4)
__device__ float d_bscore[NB * BEAMW];
__device__ unsigned g_cnt = 0;
__device__ unsigned g_gen = 0;

// ---------------- grid barrier (pure spin, no nanosleep) ----------------
__device__ __forceinline__ void gbar() {
    __syncthreads();
    if (threadIdx.x == 0) {
        volatile unsigned* gen = &g_gen;
        unsigned my = *gen;
        __threadfence();
        if (atomicAdd(&g_cnt, 1u) == (unsigned)(G - 1)) {
            g_cnt = 0;
            __threadfence();
            *gen = my + 1u;
        } else {
            while (*gen == my) { }
        }
        __threadfence();
    }
    __syncthreads();
}

// ---------------- helpers ----------------
__device__ __forceinline__ float geluf(float x) {
    return 0.5f * x * (1.0f + erff(x * 0.7071067811865476f));
}
__device__ __forceinline__ float sigmoidf_(float x) {
    return 1.0f / (1.0f + expf(-x));
}

// two independent 256-thread halves of the first 512 threads
__device__ __forceinline__ float halfReduceSum(float v, float* sbuf) {
    int tid = threadIdx.x;
    #pragma unroll
    for (int o = 16; o > 0; o >>= 1) v += __shfl_down_sync(0xffffffffu, v, o);
    if ((tid & 31) == 0) sbuf[tid >> 5] = v;
    __syncthreads();
    int h = tid >> 8;
    float r = 0.f;
    #pragma unroll
    for (int w = 0; w < 8; w++) r += sbuf[h * 8 + w];
    __syncthreads();
    return r;
}

// ---------------- packed f32x2 FFMA ----------------
__device__ __forceinline__ unsigned long long pack2(float lo, float hi) {
    unsigned long long r;
    asm("mov.b64 %0, {%1, %2};" : "=l"(r) : "f"(lo), "f"(hi));
    return r;
}
__device__ __forceinline__ void fma2(unsigned long long& d, unsigned long long a,
                                     unsigned long long b) {
    asm("fma.rn.f32x2 %0, %1, %2, %0;" : "+l"(d) : "l"(a), "l"(b));
}
__device__ __forceinline__ void unpack2(unsigned long long v, float& lo, float& hi) {
    asm("mov.b64 {%0, %1}, %2;" : "=f"(lo), "=f"(hi) : "l"(v));
}

// ---------------- 64x64 tile GEMM job, K-slice 256 = 4 teams x 64 ----------------
// Raw output (no bias/act). mode=1: A := gelu(A + A2 + gb[k]) elementwise on load.
// thread layout per team (128 thr): warp w covers rows w*16..+15;
// lane: rq=lane>>3 -> rows w*16+rq*4..+3 ; cg=lane&7 -> cols cg*8..+7
__device__ void gemm_job(const float* __restrict__ A, const float* __restrict__ A2,
                         const float* __restrict__ gb, int mode,
                         int lda, int k0,
                         const float* __restrict__ B, int ldb,
                         float* __restrict__ C, int ldc, char* dsm) {
    int tid  = threadIdx.x;
    int team = tid >> 7;
    int ttid = tid & 127;
    float* sA = (float*)(dsm + team * TEAM_BYTES);           // [64 kk][68]
    float* sB = (float*)(dsm + team * TEAM_BYTES + 17408);   // [64 kk][64]
    int kt = k0 + team * 64;

    // stage A (transpose to [kk][row]): k4 = ttid>>3 (0..15), r0 = ttid&7
    {
        int k4 = ttid >> 3;
        int r0 = ttid & 7;
        #pragma unroll
        for (int p = 0; p < 8; p++) {
            int row = r0 + p * 8;
            float4 v = *(const float4*)(A + (size_t)row * lda + kt + k4 * 4);
            if (mode) {
                float4 v2 = *(const float4*)(A2 + (size_t)row * lda + kt + k4 * 4);
                float4 bb = *(const float4*)(gb + kt + k4 * 4);
                v.x = geluf(v.x + v2.x + bb.x);
                v.y = geluf(v.y + v2.y + bb.y);
                v.z = geluf(v.z + v2.z + bb.z);
                v.w = geluf(v.w + v2.w + bb.w);
            }
            sA[(k4 * 4 + 0) * 68 + row] = v.x;
            sA[(k4 * 4 + 1) * 68 + row] = v.y;
            sA[(k4 * 4 + 2) * 68 + row] = v.z;
            sA[(k4 * 4 + 3) * 68 + row] = v.w;
        }
    }
    // stage B: c4 = ttid&15, kr = ttid>>4 (+8 per pass)
    {
        int c4 = ttid & 15;
        #pragma unroll
        for (int p = 0; p < 8; p++) {
            int kloc = (ttid >> 4) + p * 8;
            *(float4*)(sB + kloc * 64 + c4 * 4) =
                *(const float4*)(B + (size_t)(kt + kloc) * ldb + c4 * 4);
        }
    }
    __syncthreads();

    int lane = ttid & 31, w = ttid >> 5;
    int arow = w * 16 + (lane >> 3) * 4;
    int bcol = (lane & 7) * 8;
    unsigned long long acc[16];
    #pragma unroll
    for (int i = 0; i < 16; i++) acc[i] = 0ull;

    #pragma unroll 8
    for (int kk = 0; kk < 64; kk++) {
        float4 av = *(const float4*)(sA + kk * 68 + arow);
        unsigned long long a0 = pack2(av.x, av.x);
        unsigned long long a1 = pack2(av.y, av.y);
        unsigned long long a2 = pack2(av.z, av.z);
        unsigned long long a3 = pack2(av.w, av.w);
        ulonglong2 b01 = *(const ulonglong2*)(sB + kk * 64 + bcol);
        ulonglong2 b23 = *(const ulonglong2*)(sB + kk * 64 + bcol + 4);
        fma2(acc[0],  a0, b01.x); fma2(acc[1],  a0, b01.y);
        fma2(acc[2],  a0, b23.x); fma2(acc[3],  a0, b23.y);
        fma2(acc[4],  a1, b01.x); fma2(acc[5],  a1, b01.y);
        fma2(acc[6],  a1, b23.x); fma2(acc[7],  a1, b23.y);
        fma2(acc[8],  a2, b01.x); fma2(acc[9],  a2, b01.y);
        fma2(acc[10], a2, b23.x); fma2(acc[11], a2, b23.y);
        fma2(acc[12], a3, b01.x); fma2(acc[13], a3, b01.y);
        fma2(acc[14], a3, b23.x); fma2(acc[15], a3, b23.y);
    }
    __syncthreads();

    float o[32];
    #pragma unroll
    for (int i = 0; i < 16; i++) unpack2(acc[i], o[2 * i], o[2 * i + 1]);

    if (team != 0) {
        float* cb = sB;   // own region, done with B data
        #pragma unroll
        for (int j = 0; j < 32; j++) cb[j * 128 + ttid] = o[j];
    }
    __syncthreads();
    if (team == 0) {
        #pragma unroll
        for (int t = 1; t < 4; t++) {
            const float* cb = (const float*)(dsm + t * TEAM_BYTES + 17408);
            #pragma unroll
            for (int j = 0; j < 32; j++) o[j] += cb[j * 128 + ttid];
        }
        #pragma unroll
        for (int j = 0; j < 4; j++) {
            *(float4*)(C + (size_t)(arow + j) * ldc + bcol) =
                make_float4(o[8 * j], o[8 * j + 1], o[8 * j + 2], o[8 * j + 3]);
            *(float4*)(C + (size_t)(arow + j) * ldc + bcol + 4) =
                make_float4(o[8 * j + 4], o[8 * j + 5], o[8 * j + 6], o[8 * j + 7]);
        }
    }
    __syncthreads();
}

// ---------------- the persistent mega kernel ----------------
__global__ void __launch_bounds__(NT, 1)
mega(const float* __restrict__ sequence, const float* __restrict__ input_mask,
     const float* __restrict__ w_init, const float* __restrict__ b_init,
     const float* __restrict__ ln1_g, const float* __restrict__ ln1_b,
     const float* __restrict__ scorer_w, const float* __restrict__ scorer_b,
     const float* __restrict__ conv_w, const float* __restrict__ conv_b,
     const float* __restrict__ start,
     const float* __restrict__ wcell1_w, const float* __restrict__ wcell1_b,
     const float* __restrict__ wcell2_w, const float* __restrict__ wcell2_b,
     const float* __restrict__ ln2_g, const float* __restrict__ ln2_b,
     float* __restrict__ out) {
    extern __shared__ char dsm[];
    __shared__ float sred[16];
    __shared__ float sscore[8];
    __shared__ int   ssel[BEAMW];

    int tid = threadIdx.x;
    int bid = blockIdx.x;
    int h   = tid >> 8;        // half id (EF / LN1)
    int col = tid & 255;

    // ---- init 1: seq = LN1(sequence @ w_init + b_init); one row per half ----
    {
        float* sX = (float*)dsm;
        for (int job = bid; job < (NB * SL) / 2; job += G) {
            int row = job * 2 + h;
            sX[h * 256 + col] = sequence[(size_t)row * DIM + col];
            __syncthreads();
            float acc = 0.f;
            for (int i = 0; i < DIM; i++)
                acc += sX[h * 256 + i] * w_init[i * DIM + col];
            float y = acc + b_init[col];
            float s1 = halfReduceSum(y, sred);
            float s2 = halfReduceSum(y * y, sred);
            float m = s1 * (1.0f / DIM);
            float var = s2 * (1.0f / DIM) - m * m;
            d_seq[(size_t)row * DIM + col] = (y - m) * rsqrtf(var + LNEPS) * ln1_g[col] + ln1_b[col];
            __syncthreads();
        }
    }
    gbar();

    // ---- init 2: stack init + first gather (K=1) ----
    if (bid < NB) {
        int n = bid;
        float* stk0 = d_stk[0] + (size_t)(n * BEAMW) * SL * DIM;
        if (h == 0) {
            stk0[col]       = d_seq[(size_t)(n * SL + 0) * DIM + col];
            stk0[DIM + col] = d_seq[(size_t)(n * SL + 1) * DIM + col];
            if (col == 0) {
                d_p[0][n * BEAMW] = (input_mask[n * SL + 1] > 0.5f) ? 1 : 0;
                d_q[0][n * BEAMW] = 0;
            }
        }
        __syncthreads();
        if (h == 0) {
            int p = d_p[0][n * BEAMW];
            float c1 = (p >= 1) ? stk0[(p - 1) * DIM + col] : start[col];
            float c2 = stk0[p * DIM + col];
            float cu = d_seq[(size_t)(n * SL + 2) * DIM + col];
            d_win[n * 768 + col]       = c1;
            d_win[n * 768 + 256 + col] = c2;
            d_win[n * 768 + 512 + col] = cu;
            d_cc[n * 512 + col]        = c1;
            d_cc[n * 512 + 256 + col]  = c2;
        }
    }
    gbar();

    int K = 1, buf = 0;
    for (int t = 2; t <= 2 * SL - 2; t++) {
        int newK = (2 * K < BEAMW) ? 2 * K : BEAMW;

        // ---- phase B: cell1 raw partials (ks2) + conv raw partials (ks3) ----
        // always M=128 padded (garbage rows finite, never read)
        for (int job = bid; job < 88; job += G) {
            if (job < 64) {
                int ks = job & 1, ct = (job >> 1) & 15, ri = job >> 5;
                gemm_job(d_cc + (size_t)ri * 64 * 512, nullptr, nullptr, 0,
                         512, ks * 256,
                         wcell1_w + ct * 64, 1024,
                         d_i1 + (size_t)ks * 131072 + (size_t)ri * 64 * 1024 + ct * 64, 1024,
                         dsm);
            } else {
                int j = job - 64;                 // 24 = ri2 x ct4 x ks3
                int ks = j % 3, r2 = j / 3;
                int ct = r2 & 3, ri = r2 >> 2;
                gemm_job(d_win + (size_t)ri * 64 * 768, nullptr, nullptr, 0,
                         768, ks * 256,
                         conv_w + ct * 64, 256,
                         d_cpart + (size_t)ks * 32768 + (size_t)ri * 64 * 256 + ct * 64, 256,
                         dsm);
            }
        }
        gbar();

        // ---- phase C: cell2 raw partials (ks4); A = gelu(i1_0 + i1_1 + b1) on load ----
        for (int job = bid; job < 128; job += G) {
            int ks = job & 3, ct = (job >> 2) & 15, ri = job >> 6;
            gemm_job(d_i1 + (size_t)ri * 64 * 1024,
                     d_i1 + 131072 + (size_t)ri * 64 * 1024,
                     wcell1_b, 1,
                     1024, ks * 256,
                     wcell2_w + ct * 64, 1024,
                     d_c2 + (size_t)ks * 131072 + (size_t)ri * 64 * 1024 + ct * 64, 1024,
                     dsm);
        }
        gbar();

        // ---- phase EF ----
        if (bid < NB) {
            int n = bid;
            float* red = (float*)dsm;    // [BEAMW][256]

            // 1. scores (two beams at a time, one per half)
            for (int k0 = 0; k0 < K; k0 += 2) {
                int k = k0 + h;
                int valid = (k < K);
                int kk2 = valid ? k : 0;
                int m = n * K + kk2;
                float s = d_cpart[m * 256 + col]
                        + d_cpart[32768 + m * 256 + col]
                        + d_cpart[65536 + m * 256 + col];
                float y = valid ? geluf(s + conv_b[col]) * scorer_w[col] : 0.f;
                float dot = halfReduceSum(y, sred);
                if (col == 0 && valid) {
                    float dec = sigmoidf_(dot + scorer_b[0]);
                    int p = d_p[buf][n * BEAMW + k];
                    int q = d_q[buf][n * BEAMW + k];
                    float lp  = (p >= 1) ? 1.0f : 0.0f;
                    float cmf = (q < SL - 2) ? input_mask[n * SL + 2 + q] : 0.0f;
                    float bz  = ((lp == 0.0f) && (cmf == 0.0f)) ? 1.0f : 0.0f;
                    float rs = cmf * dec + (1.0f - cmf);
                    rs = lp * rs;
                    rs = bz + (1.0f - bz) * rs;
                    rs = logf(rs + EPSC);
                    float ss = lp * (1.0f - dec) + (1.0f - lp);
                    ss = cmf * ss;
                    ss = (1.0f - bz) * ss;
                    ss = logf(ss + EPSC);
                    sscore[k] = rs;
                    sscore[4 + k] = ss;
                }
            }
            // 2. compose (sum 4 cell2 partials + bias -> gates + LN2)
            for (int k0 = 0; k0 < K; k0 += 2) {
                int k = k0 + h;
                int valid = (k < K);
                int kk2 = valid ? k : 0;
                int m = n * K + kk2;
                const float* c0 = d_c2 + (size_t)m * 1024;
                float v0 = c0[col]       + c0[131072 + col]       + c0[262144 + col]       + c0[393216 + col]       + wcell2_b[col];
                float v1 = c0[256 + col] + c0[131072 + 256 + col] + c0[262144 + 256 + col] + c0[393216 + 256 + col] + wcell2_b[256 + col];
                float v2 = c0[512 + col] + c0[131072 + 512 + col] + c0[262144 + 512 + col] + c0[393216 + 512 + col] + wcell2_b[512 + col];
                float v3 = c0[768 + col] + c0[131072 + 768 + col] + c0[262144 + 768 + col] + c0[393216 + 768 + col] + wcell2_b[768 + col];
                float x = sigmoidf_(v0) * d_cc[m * 512 + col]
                        + sigmoidf_(v1) * d_cc[m * 512 + 256 + col]
                        + sigmoidf_(v2) * v3;
                float xm = valid ? x : 0.f;
                float s1 = halfReduceSum(xm, sred);
                float s2 = halfReduceSum(xm * xm, sred);
                if (valid) {
                    float mn = s1 * (1.0f / DIM);
                    float var = s2 * (1.0f / DIM) - mn * mn;
                    red[k * 256 + col] = (x - mn) * rsqrtf(var + LNEPS) * ln2_g[col] + ln2_b[col];
                }
            }
            __syncthreads();
            // 3. stable top-k
            if (tid == 0) {
                int C2 = 2 * K;
                float sc[8];
                for (int c = 0; c < C2; c++)
                    sc[c] = (c < K) ? sscore[c] : sscore[4 + (c - K)];
                if (C2 <= BEAMW) {
                    for (int s = 0; s < C2; s++) { ssel[s] = s; d_bscore[n * BEAMW + s] = sc[s]; }
                } else {
                    bool used[8];
                    for (int c = 0; c < C2; c++) used[c] = false;
                    for (int s = 0; s < BEAMW; s++) {
                        int best = -1; float bv = 0.f;
                        for (int c = 0; c < C2; c++) {
                            if (used[c]) continue;
                            if (best < 0 || sc[c] > bv) { best = c; bv = sc[c]; }
                        }
                        used[best] = true;
                        ssel[s] = best;
                        d_bscore[n * BEAMW + s] = bv;
                    }
                }
            }
            __syncthreads();
            // 4. beam copy (one beam per half)
            int nb2 = buf ^ 1;
            for (int s = h; s < newK; s += 2) {
                int c = ssel[s];
                int isred = (c < K);
                int k = isred ? c : (c - K);
                int p = d_p[buf][n * BEAMW + k];
                int q = d_q[buf][n * BEAMW + k];
                int lp = (p >= 1);
                float cmf = (q < SL - 2) ? input_mask[n * SL + 2 + q] : 0.0f;
                int cm = (cmf > 0.5f);
                int wr_pos = -1, newp = p, newq = q;
                const float* wr_g = nullptr;
                int wr_sm = 0;
                if (isred) {
                    if (lp) { wr_pos = p - 1; newp = p - 1; wr_sm = 1; }
                } else {
                    newq = q + 1;
                    if (cm) { wr_pos = p + 1; newp = p + 1; wr_g = &d_seq[(size_t)(n * SL + 2 + q) * DIM]; }
                }
                const float* src = d_stk[buf] + (size_t)(n * BEAMW + k) * SL * DIM;
                float* dst       = d_stk[nb2] + (size_t)(n * BEAMW + s) * SL * DIM;
                int len = (newp + 1) * DIM;
                for (int idx = col; idx < len; idx += 256) {
                    int pos = idx >> 8;
                    float v = (pos == wr_pos) ? (wr_sm ? red[k * 256 + (idx & 255)]
                                                       : wr_g[idx & 255])
                                              : src[idx];
                    dst[idx] = v;
                }
                if (col == 0) {
                    d_p[nb2][n * BEAMW + s] = newp;
                    d_q[nb2][n * BEAMW + s] = newq;
                }
            }
            __syncthreads();
            // 5. gather for next iteration
            for (int s = h; s < newK; s += 2) {
                int m2 = n * newK + s;
                int p = d_p[nb2][n * BEAMW + s];
                int q = d_q[nb2][n * BEAMW + s];
                const float* stk = d_stk[nb2] + (size_t)(n * BEAMW + s) * SL * DIM;
                float c1 = (p >= 1) ? stk[(p - 1) * DIM + col] : start[col];
                float c2 = stk[p * DIM + col];
                float cu = (q < SL - 2) ? d_seq[(size_t)(n * SL + 2 + q) * DIM + col] : 0.f;
                d_win[m2 * 768 + col]       = c1;
                d_win[m2 * 768 + 256 + col] = c2;
                d_win[m2 * 768 + 512 + col] = cu;
                d_cc[m2 * 512 + col]        = c1;
                d_cc[m2 * 512 + 256 + col]  = c2;
            }
        }
        gbar();
        buf ^= 1;
        K = newK;
    }

    // ---- final ----
    if (bid < NB && h == 0) {
        int n = bid;
        float sc[BEAMW];
        float mx = -1e30f;
        #pragma unroll
        for (int k = 0; k < BEAMW; k++) {
            sc[k] = d_bscore[n * BEAMW + k];
            mx = fmaxf(mx, sc[k]);
        }
        float e[BEAMW], sum = 0.f;
        #pragma unroll
        for (int k = 0; k < BEAMW; k++) { e[k] = expf(sc[k] - mx); sum += e[k]; }
        float o = 0.f;
        #pragma unroll
        for (int k = 0; k < BEAMW; k++) {
            int p = d_p[buf][n * BEAMW + k];
            o += (e[k] / sum) * d_stk[buf][((size_t)(n * BEAMW + k) * SL + p) * DIM + col];
        }
        out[(size_t)n * DIM + col] = o;
    }
}

// ---------------- host launcher ----------------
extern "C" void kernel_launch(void* const* d_in, const int* in_sizes, int n_in,
                              void* d_out, int out_size) {
    const float* sequence   = (const float*)d_in[0];
    const float* input_mask = (const float*)d_in[1];
    const float* w_init     = (const float*)d_in[2];
    const float* b_init     = (const float*)d_in[3];
    const float* ln1_g      = (const float*)d_in[4];
    const float* ln1_b      = (const float*)d_in[5];
    const float* scorer_w   = (const float*)d_in[6];
    const float* scorer_b   = (const float*)d_in[7];
    const float* conv_w     = (const float*)d_in[8];
    const float* conv_b     = (const float*)d_in[9];
    const float* start      = (const float*)d_in[10];
    const float* wcell1_w   = (const float*)d_in[11];
    const float* wcell1_b   = (const float*)d_in[12];
    const float* wcell2_w   = (const float*)d_in[13];
    const float* wcell2_b   = (const float*)d_in[14];
    const float* ln2_g      = (const float*)d_in[15];
    const float* ln2_b      = (const float*)d_in[16];
    float* out = (float*)d_out;

    cudaFuncSetAttribute(mega, cudaFuncAttributeMaxDynamicSharedMemorySize, SMEM_DYN);
    mega<<<G, NT, SMEM_DYN>>>(sequence, input_mask, w_init, b_init, ln1_g, ln1_b,
                              scorer_w, scorer_b, conv_w, conv_b, start,
                              wcell1_w, wcell1_b, wcell2_w, wcell2_b, ln2_g, ln2_b, out);
}